// round 6
// baseline (speedup 1.0000x reference)
#include <cuda_runtime.h>
#include <cstdint>
#include <math.h>

// Problem: B=2,H=16,Q=4096,D=128,KV=10521,G=16,KP=1536,BM=256
#define NBH    32
#define QLEN   4096
#define DIM    128
#define KVLEN  10521
#define NG     16
#define KPAD   1536
#define QT     128
#define KT     64
#define NTILES (KPAD / KT)   // 24
#define NTHR   256

// smem byte offsets (rows XOR-swizzled in 16B chunks by (row&7))
#define SQ   0                         // Q:  128 x 512B (tf32 rna, pre-scaled)
#define SK   (SQ  + 128 * 512)         // K:  2 x (64 x 512B)  raw fp32 via cp.async
#define SVT  (SK  + 2 * 64 * 512)      // VT: 2 x (128 x 256B) raw fp32, kv sigma-permuted
#define SM_TOTAL (SVT + 2 * 128 * 256) // 196608 B
#define KBUF 32768
#define VBUF 32768

__device__ __forceinline__ uint32_t smem_u32(const void* p) {
    uint32_t a;
    asm("{ .reg .u64 t; cvta.to.shared.u64 t, %1; cvt.u32.u64 %0, t; }" : "=r"(a) : "l"(p));
    return a;
}
__device__ __forceinline__ uint32_t f2tf32(float x) {
    uint32_t r; asm("cvt.rna.tf32.f32 %0, %1;" : "=r"(r) : "f"(x)); return r;
}
__device__ __forceinline__ void cpa16(uint32_t dst, const void* src) {
    asm volatile("cp.async.cg.shared.global [%0], [%1], 16;" :: "r"(dst), "l"(src));
}
__device__ __forceinline__ void cpa4(uint32_t dst, const void* src) {
    asm volatile("cp.async.ca.shared.global [%0], [%1], 4;" :: "r"(dst), "l"(src));
}
#define CP_COMMIT() asm volatile("cp.async.commit_group;" ::: "memory")
#define CP_WAIT(n)  asm volatile("cp.async.wait_group %0;" :: "n"(n) : "memory")

__device__ __forceinline__ void mma_tf32(float* d, uint32_t a0, uint32_t a1,
                                         uint32_t a2, uint32_t a3,
                                         uint32_t b0, uint32_t b1) {
    asm volatile(
        "mma.sync.aligned.m16n8k8.row.col.f32.tf32.tf32.f32 "
        "{%0,%1,%2,%3}, {%4,%5,%6,%7}, {%8,%9}, {%0,%1,%2,%3};"
        : "+f"(d[0]), "+f"(d[1]), "+f"(d[2]), "+f"(d[3])
        : "r"(a0), "r"(a1), "r"(a2), "r"(a3), "r"(b0), "r"(b1));
}
__device__ __forceinline__ uint4 lds128(const char* p) {
    return *(const uint4*)p;
}
#define RNA 0x1000u   // +half-ulp of tf32 before HW truncation == round-nearest-away

__global__ void __launch_bounds__(NTHR, 1)
sparse_attn_mma(const float* __restrict__ q,
                const float* __restrict__ k,
                const float* __restrict__ v,
                const int*   __restrict__ inds,
                float*       __restrict__ out)
{
    extern __shared__ __align__(128) char sm[];
    const uint32_t sbu = smem_u32(sm);

    const int tid  = threadIdx.x;
    const int wid  = tid >> 5;
    const int lane = tid & 31;
    const int lq   = lane >> 2;     // 0..7
    const int lr   = lane & 3;      // 0..3

    const int bid = blockIdx.x;
    const int qt  = bid & 1;
    const int g   = (bid >> 1) & 15;
    const int bh  = bid >> 5;
    const int qbase = g * 256 + qt * QT;

    const float* qp = q + ((size_t)bh * QLEN + qbase) * DIM;
    const float* kb = k + (size_t)bh * KVLEN * DIM;
    const float* vb = v + (size_t)bh * KVLEN * DIM;
    const int*   ib = inds + ((size_t)bh * NG + g) * KPAD;
    float*       op = out + ((size_t)bh * QLEN + qbase) * DIM;

    const float scale = 0.088388347648318447f;   // 1/sqrt(128)

    // ---- gather (cp.async). VT is stored with kv permutation sigma so that the
    //      S-accumulator register layout IS the PV A-fragment layout (P in regs).
    #define ISSUE_GATHER(tt, buf) do {                                            \
        const int* ibn = ib + (tt) * KT;                                          \
        const uint32_t skn = sbu + SK  + (buf) * KBUF;                            \
        const uint32_t svn = sbu + SVT + (buf) * VBUF;                            \
        _Pragma("unroll")                                                         \
        for (int i = 0; i < 8; ++i) {                                             \
            const int e = tid + i * NTHR;                                         \
            const int row = e >> 5, c = e & 31;                                   \
            const int gi = __ldg(ibn + row);                                      \
            cpa16(skn + row * 512 + ((16 * c) ^ ((row & 7) << 4)),                \
                  kb + (size_t)gi * DIM + 4 * c);                                 \
        }                                                                         \
        _Pragma("unroll")                                                         \
        for (int i = 0; i < 8; ++i) {                                             \
            const int p  = wid + 8 * i;                                           \
            const int rr = p & 15;                                                \
            const int dd = (p >> 4) * 32 + lane;                                  \
            const int sbase = 16 * (rr >> 2) + 2 * (rr & 3);                      \
            const uint32_t dbase = svn + dd * 256 +                               \
                (((16 * rr) & 0x7F) ^ ((dd & 7) << 4)) + ((16 * rr) & 0x80);      \
            const int g0 = __ldg(ibn + sbase + 0);                                \
            const int g1 = __ldg(ibn + sbase + 1);                                \
            const int g2 = __ldg(ibn + sbase + 8);                                \
            const int g3 = __ldg(ibn + sbase + 9);                                \
            cpa4(dbase + 0,  vb + (size_t)g0 * DIM + dd);                         \
            cpa4(dbase + 4,  vb + (size_t)g1 * DIM + dd);                         \
            cpa4(dbase + 8,  vb + (size_t)g2 * DIM + dd);                         \
            cpa4(dbase + 12, vb + (size_t)g3 * DIM + dd);                         \
        }                                                                         \
    } while (0)

    // ---- prologue: start gather(0); load Q (rna + pre-scale) meanwhile ----
    ISSUE_GATHER(0, 0);
    CP_COMMIT();

    #pragma unroll
    for (int i = 0; i < 16; ++i) {
        const int e   = tid + i * NTHR;
        const int row = e >> 5, c = e & 31;
        float4 val = ((const float4*)(qp + (size_t)row * DIM))[c];
        uint4 u;
        u.x = f2tf32(val.x * scale); u.y = f2tf32(val.y * scale);
        u.z = f2tf32(val.z * scale); u.w = f2tf32(val.w * scale);
        *(uint4*)(sm + SQ + row * 512 + ((16 * c) ^ ((row & 7) << 4))) = u;
    }

    // per-thread constant addressing
    const int qrow  = wid * 16 + lq;
    const int xorA  = (qrow & 7) << 4;
    const char* rbA0 = sm + SQ + qrow * 512;
    const char* rbA1 = rbA0 + 8 * 512;
    const int  xorB  = lq << 4;

    float oacc[16][4];
    #pragma unroll
    for (int j = 0; j < 16; ++j)
        #pragma unroll
        for (int c = 0; c < 4; ++c) oacc[j][c] = 0.0f;
    float l0 = 0.0f, l1 = 0.0f;

    for (int t = 0; t < NTILES; ++t) {
        if (t + 1 < NTILES) {
            ISSUE_GATHER(t + 1, (t + 1) & 1);
            CP_COMMIT();
            CP_WAIT(1);
        } else {
            CP_WAIT(0);
        }
        __syncthreads();

        const char* rbK = sm + SK  + (t & 1) * KBUF + lq * 512;
        const char* rbV = sm + SVT + (t & 1) * VBUF + lq * 256;

        // ---- QK: S[16 x 64] per warp; lds128 frags; rna-round K ----
        float sacc[8][4];
        #pragma unroll
        for (int j = 0; j < 8; ++j)
            #pragma unroll
            for (int c = 0; c < 4; ++c) sacc[j][c] = 0.0f;

        #pragma unroll
        for (int pr = 0; pr < 8; ++pr) {
            const int abyte = (64 * pr + 16 * lr) ^ xorA;
            const uint4 A0 = lds128(rbA0 + abyte);
            const uint4 A1 = lds128(rbA1 + abyte);
            const int bbyte = (64 * pr + 16 * lr) ^ xorB;
            #pragma unroll
            for (int j = 0; j < 8; ++j) {
                uint4 B = lds128(rbK + j * (8 * 512) + bbyte);
                B.x += RNA; B.y += RNA; B.z += RNA; B.w += RNA;
                mma_tf32(sacc[j], A0.x, A1.x, A0.y, A1.y, B.x, B.y);
                mma_tf32(sacc[j], A0.z, A1.z, A0.w, A1.w, B.z, B.w);
            }
        }

        // ---- softmax: exp, row sums, P -> registers (PV A-frag order) ----
        uint32_t* pf = reinterpret_cast<uint32_t*>(&sacc[0][0]);
        float sA = 0.0f, sB = 0.0f;
        #pragma unroll
        for (int j = 0; j < 8; ++j) {
            const float e0 = __expf(fminf(sacc[j][0], 60.0f));
            const float e1 = __expf(fminf(sacc[j][1], 60.0f));
            const float e2 = __expf(fminf(sacc[j][2], 60.0f));
            const float e3 = __expf(fminf(sacc[j][3], 60.0f));
            sA += e0 + e1;  sB += e2 + e3;
            pf[4 * j + 0] = f2tf32(e0);   // a0: row lq,   k-slot lr
            pf[4 * j + 1] = f2tf32(e2);   // a1: row lq+8, k-slot lr
            pf[4 * j + 2] = f2tf32(e1);   // a2: row lq,   k-slot lr+4
            pf[4 * j + 3] = f2tf32(e3);   // a3: row lq+8, k-slot lr+4
        }
        sA += __shfl_xor_sync(0xffffffffu, sA, 1);
        sA += __shfl_xor_sync(0xffffffffu, sA, 2);
        sB += __shfl_xor_sync(0xffffffffu, sB, 1);
        sB += __shfl_xor_sync(0xffffffffu, sB, 2);
        l0 += sA;  l1 += sB;

        // ---- PV: O[16 x 128] += P x V ; P from regs; rna-round V ----
        #pragma unroll
        for (int pr = 0; pr < 4; ++pr) {
            const int vv = 64 * pr + 16 * lr;
            const int vbyte = ((vv & 0x7F) ^ xorB) + (vv & 0x80);
            const uint32_t* pa = pf + 8 * pr;
            #pragma unroll
            for (int j = 0; j < 16; ++j) {
                uint4 B = lds128(rbV + j * (8 * 256) + vbyte);
                B.x += RNA; B.y += RNA; B.z += RNA; B.w += RNA;
                mma_tf32(oacc[j], pa[0], pa[1], pa[2], pa[3], B.x, B.y);
                mma_tf32(oacc[j], pa[4], pa[5], pa[6], pa[7], B.z, B.w);
            }
        }
        __syncthreads();   // buf (t&1) free for gather(t+2)
    }

    // ---- epilogue: divide by l, store ----
    const float inv0 = 1.0f / l0;
    const float inv1 = 1.0f / l1;
    float* orow0 = op + (size_t)(wid * 16 + lq) * DIM;
    float* orow1 = orow0 + 8 * DIM;
    #pragma unroll
    for (int j = 0; j < 16; ++j) {
        const int col = 8 * j + 2 * lr;
        float2 r0, r1;
        r0.x = oacc[j][0] * inv0;  r0.y = oacc[j][1] * inv0;
        r1.x = oacc[j][2] * inv1;  r1.y = oacc[j][3] * inv1;
        *(float2*)(orow0 + col) = r0;
        *(float2*)(orow1 + col) = r1;
    }
}

extern "C" void kernel_launch(void* const* d_in, const int* in_sizes, int n_in,
                              void* d_out, int out_size)
{
    const float* q    = (const float*)d_in[0];
    const float* k    = (const float*)d_in[1];
    const float* v    = (const float*)d_in[2];
    const int*   inds = (const int*)d_in[3];
    float*       out  = (float*)d_out;

    cudaFuncSetAttribute(sparse_attn_mma,
                         cudaFuncAttributeMaxDynamicSharedMemorySize, SM_TOTAL);

    const int grid = NBH * NG * 2;   // 1024
    sparse_attn_mma<<<grid, NTHR, SM_TOTAL>>>(q, k, v, inds, out);
}

// round 8
// speedup vs baseline: 1.3335x; 1.3335x over previous
#include <cuda_runtime.h>
#include <cstdint>
#include <math.h>

// Problem: B=2,H=16,Q=4096,D=128,KV=10521,G=16,KP=1536,BM=256
#define NBH    32
#define QLEN   4096
#define DIM    128
#define KVLEN  10521
#define NG     16
#define KPAD   1536
#define QT     128
#define KT     64
#define NTILES (KPAD / KT)   // 24
#define NTHR   256

// smem byte offsets
#define SQ   0                         // Q:  128 x 512B (tf32 rna, pre-scaled)
#define SK   (SQ  + 128 * 512)         // K:  2 x (64 x 512B)  raw fp32 via cp.async
#define SVT  (SK  + 2 * 64 * 512)      // VT: 2 x (128 x 256B) raw fp32, kv sigma-permuted
#define SM_TOTAL (SVT + 2 * 128 * 256) // 196608 B
#define KBUF 32768
#define VBUF 32768

// conflict-aware chunk swizzle: phase rows 2p,2p+1 get XORs differing in bit 2
__host__ __device__ __forceinline__ int swz(int r) { return ((r & 1) << 2) | (r >> 1); }

__device__ __forceinline__ uint32_t smem_u32(const void* p) {
    uint32_t a;
    asm("{ .reg .u64 t; cvta.to.shared.u64 t, %1; cvt.u32.u64 %0, t; }" : "=r"(a) : "l"(p));
    return a;
}
__device__ __forceinline__ uint32_t f2tf32(float x) {
    uint32_t r; asm("cvt.rna.tf32.f32 %0, %1;" : "=r"(r) : "f"(x)); return r;
}
__device__ __forceinline__ void cpa16(uint32_t dst, const void* src) {
    asm volatile("cp.async.cg.shared.global [%0], [%1], 16;" :: "r"(dst), "l"(src));
}
__device__ __forceinline__ void cpa4(uint32_t dst, const void* src) {
    asm volatile("cp.async.ca.shared.global [%0], [%1], 4;" :: "r"(dst), "l"(src));
}
#define CP_COMMIT() asm volatile("cp.async.commit_group;" ::: "memory")
#define CP_WAIT(n)  asm volatile("cp.async.wait_group %0;" :: "n"(n) : "memory")

__device__ __forceinline__ void mma_tf32(float* d, uint32_t a0, uint32_t a1,
                                         uint32_t a2, uint32_t a3,
                                         uint32_t b0, uint32_t b1) {
    asm volatile(
        "mma.sync.aligned.m16n8k8.row.col.f32.tf32.tf32.f32 "
        "{%0,%1,%2,%3}, {%4,%5,%6,%7}, {%8,%9}, {%0,%1,%2,%3};"
        : "+f"(d[0]), "+f"(d[1]), "+f"(d[2]), "+f"(d[3])
        : "r"(a0), "r"(a1), "r"(a2), "r"(a3), "r"(b0), "r"(b1));
}
__device__ __forceinline__ uint4 lds128(const char* p) {
    return *(const uint4*)p;
}
#define RNA 0x1000u   // +half-ulp of tf32 before HW truncation == round-nearest-away

__global__ void __launch_bounds__(NTHR, 1)
sparse_attn_mma(const float* __restrict__ q,
                const float* __restrict__ k,
                const float* __restrict__ v,
                const int*   __restrict__ inds,
                float*       __restrict__ out)
{
    extern __shared__ __align__(128) char sm[];
    const uint32_t sbu = smem_u32(sm);

    const int tid  = threadIdx.x;
    const int wid  = tid >> 5;
    const int lane = tid & 31;
    const int lq   = lane >> 2;     // 0..7
    const int lr   = lane & 3;      // 0..3

    const int bid = blockIdx.x;
    const int qt  = bid & 1;
    const int g   = (bid >> 1) & 15;
    const int bh  = bid >> 5;
    const int qbase = g * 256 + qt * QT;

    const float* qp = q + ((size_t)bh * QLEN + qbase) * DIM;
    const float* kb = k + (size_t)bh * KVLEN * DIM;
    const float* vb = v + (size_t)bh * KVLEN * DIM;
    const int*   ib = inds + ((size_t)bh * NG + g) * KPAD;
    float*       op = out + ((size_t)bh * QLEN + qbase) * DIM;

    const float scale = 0.088388347648318447f;   // 1/sqrt(128)

    // ---- gather (cp.async). VT stored with kv permutation so S-accum regs
    //      are exactly the PV A-fragment (P never touches smem).
    #define ISSUE_GATHER(tt, buf) do {                                            \
        const int* ibn = ib + (tt) * KT;                                          \
        const uint32_t skn = sbu + SK  + (buf) * KBUF;                            \
        const uint32_t svn = sbu + SVT + (buf) * VBUF;                            \
        _Pragma("unroll")                                                         \
        for (int i = 0; i < 8; ++i) {                                             \
            const int e = tid + i * NTHR;                                         \
            const int row = e >> 5, c = e & 31;                                   \
            const int gi = __ldg(ibn + row);                                      \
            cpa16(skn + row * 512 + ((16 * c) ^ (swz(row & 7) << 4)),             \
                  kb + (size_t)gi * DIM + 4 * c);                                 \
        }                                                                         \
        _Pragma("unroll")                                                         \
        for (int i = 0; i < 8; ++i) {                                             \
            const int p  = wid + 8 * i;                                           \
            const int rr = p & 15;                                                \
            const int dd = (p >> 4) * 32 + lane;                                  \
            const int sbase = 16 * (rr >> 2) + 2 * (rr & 3);                      \
            const uint32_t dbase = svn + dd * 256 +                               \
                (((16 * rr) & 0x7F) ^ (swz(dd & 7) << 4)) + ((16 * rr) & 0x80);   \
            const int g0 = __ldg(ibn + sbase + 0);                                \
            const int g1 = __ldg(ibn + sbase + 1);                                \
            const int g2 = __ldg(ibn + sbase + 8);                                \
            const int g3 = __ldg(ibn + sbase + 9);                                \
            cpa4(dbase + 0,  vb + (size_t)g0 * DIM + dd);                         \
            cpa4(dbase + 4,  vb + (size_t)g1 * DIM + dd);                         \
            cpa4(dbase + 8,  vb + (size_t)g2 * DIM + dd);                         \
            cpa4(dbase + 12, vb + (size_t)g3 * DIM + dd);                         \
        }                                                                         \
    } while (0)

    // ---- prologue: start gather(0); load Q (rna + pre-scale) meanwhile ----
    ISSUE_GATHER(0, 0);
    CP_COMMIT();

    #pragma unroll
    for (int i = 0; i < 16; ++i) {
        const int e   = tid + i * NTHR;
        const int row = e >> 5, c = e & 31;
        float4 val = ((const float4*)(qp + (size_t)row * DIM))[c];
        uint4 u;
        u.x = f2tf32(val.x * scale); u.y = f2tf32(val.y * scale);
        u.z = f2tf32(val.z * scale); u.w = f2tf32(val.w * scale);
        *(uint4*)(sm + SQ + row * 512 + ((16 * c) ^ (swz(row & 7) << 4))) = u;
    }

    // per-thread constant addressing
    const int qrow  = wid * 16 + lq;
    const int xorA  = swz(qrow & 7) << 4;
    const char* rbA0 = sm + SQ + qrow * 512;
    const char* rbA1 = rbA0 + 8 * 512;
    const int  xorB  = swz(lq) << 4;

    float oacc[16][4];
    #pragma unroll
    for (int j = 0; j < 16; ++j)
        #pragma unroll
        for (int c = 0; c < 4; ++c) oacc[j][c] = 0.0f;
    float l0 = 0.0f, l1 = 0.0f;

    for (int t = 0; t < NTILES; ++t) {
        if (t + 1 < NTILES) {
            ISSUE_GATHER(t + 1, (t + 1) & 1);
            CP_COMMIT();
            CP_WAIT(1);
        } else {
            CP_WAIT(0);
        }
        __syncthreads();

        const char* rbK = sm + SK  + (t & 1) * KBUF + lq * 512;
        const char* rbV = sm + SVT + (t & 1) * VBUF + lq * 256;

        // ---- QK: S[16 x 64] per warp; conflict-free lds128 frags; rna K ----
        float sacc[8][4];
        #pragma unroll
        for (int j = 0; j < 8; ++j)
            #pragma unroll
            for (int c = 0; c < 4; ++c) sacc[j][c] = 0.0f;

        #pragma unroll
        for (int pr = 0; pr < 8; ++pr) {
            const int abyte = (64 * pr + 16 * lr) ^ xorA;
            const uint4 A0 = lds128(rbA0 + abyte);
            const uint4 A1 = lds128(rbA1 + abyte);
            const int bbyte = (64 * pr + 16 * lr) ^ xorB;
            #pragma unroll
            for (int j = 0; j < 8; ++j) {
                uint4 B = lds128(rbK + j * (8 * 512) + bbyte);
                B.x += RNA; B.y += RNA; B.z += RNA; B.w += RNA;
                mma_tf32(sacc[j], A0.x, A1.x, A0.y, A1.y, B.x, B.y);
                mma_tf32(sacc[j], A0.z, A1.z, A0.w, A1.w, B.z, B.w);
            }
        }

        // ---- softmax: exp, row sums, P -> registers (PV A-frag order) ----
        uint32_t* pf = reinterpret_cast<uint32_t*>(&sacc[0][0]);
        float sA = 0.0f, sB = 0.0f;
        #pragma unroll
        for (int j = 0; j < 8; ++j) {
            const float e0 = __expf(fminf(sacc[j][0], 60.0f));
            const float e1 = __expf(fminf(sacc[j][1], 60.0f));
            const float e2 = __expf(fminf(sacc[j][2], 60.0f));
            const float e3 = __expf(fminf(sacc[j][3], 60.0f));
            sA += e0 + e1;  sB += e2 + e3;
            pf[4 * j + 0] = f2tf32(e0);   // a0: row lq,   k-slot lr
            pf[4 * j + 1] = f2tf32(e2);   // a1: row lq+8, k-slot lr
            pf[4 * j + 2] = f2tf32(e1);   // a2: row lq,   k-slot lr+4
            pf[4 * j + 3] = f2tf32(e3);   // a3: row lq+8, k-slot lr+4
        }
        sA += __shfl_xor_sync(0xffffffffu, sA, 1);
        sA += __shfl_xor_sync(0xffffffffu, sA, 2);
        sB += __shfl_xor_sync(0xffffffffu, sB, 1);
        sB += __shfl_xor_sync(0xffffffffu, sB, 2);
        l0 += sA;  l1 += sB;

        // ---- PV: O[16 x 128] += P x V ; P from regs; rna V ----
        #pragma unroll
        for (int pr = 0; pr < 4; ++pr) {
            const int vv = 64 * pr + 16 * lr;
            const int vbyte = ((vv & 0x7F) ^ xorB) + (vv & 0x80);
            const uint32_t* pa = pf + 8 * pr;
            #pragma unroll
            for (int j = 0; j < 16; ++j) {
                uint4 B = lds128(rbV + j * (8 * 256) + vbyte);
                B.x += RNA; B.y += RNA; B.z += RNA; B.w += RNA;
                mma_tf32(oacc[j], pa[0], pa[1], pa[2], pa[3], B.x, B.y);
                mma_tf32(oacc[j], pa[4], pa[5], pa[6], pa[7], B.z, B.w);
            }
        }
        __syncthreads();   // buf (t&1) free for gather(t+2)
    }

    // ---- epilogue: divide by l, store ----
    const float inv0 = 1.0f / l0;
    const float inv1 = 1.0f / l1;
    float* orow0 = op + (size_t)(wid * 16 + lq) * DIM;
    float* orow1 = orow0 + 8 * DIM;
    #pragma unroll
    for (int j = 0; j < 16; ++j) {
        const int col = 8 * j + 2 * lr;
        float2 r0, r1;
        r0.x = oacc[j][0] * inv0;  r0.y = oacc[j][1] * inv0;
        r1.x = oacc[j][2] * inv1;  r1.y = oacc[j][3] * inv1;
        *(float2*)(orow0 + col) = r0;
        *(float2*)(orow1 + col) = r1;
    }
}

extern "C" void kernel_launch(void* const* d_in, const int* in_sizes, int n_in,
                              void* d_out, int out_size)
{
    const float* q    = (const float*)d_in[0];
    const float* k    = (const float*)d_in[1];
    const float* v    = (const float*)d_in[2];
    const int*   inds = (const int*)d_in[3];
    float*       out  = (float*)d_out;

    cudaFuncSetAttribute(sparse_attn_mma,
                         cudaFuncAttributeMaxDynamicSharedMemorySize, SM_TOTAL);

    const int grid = NBH * NG * 2;   // 1024
    sparse_attn_mma<<<grid, NTHR, SM_TOTAL>>>(q, k, v, inds, out);
}

// round 10
// speedup vs baseline: 1.3614x; 1.0209x over previous
#include <cuda_runtime.h>
#include <cstdint>
#include <math.h>

// Problem: B=2,H=16,Q=4096,D=128,KV=10521,G=16,KP=1536,BM=256
#define NBH    32
#define QLEN   4096
#define DIM    128
#define KVLEN  10521
#define NG     16
#define KPAD   1536
#define QT     256           // whole query group per CTA
#define KT     64
#define NTILES (KPAD / KT)   // 24
#define NTHR   256

// smem byte offsets (single-buffered K/VT; pipelined in time)
#define SQ   0                        // Q:  256 x 512B (tf32 rna, pre-scaled) = 128KB
#define SK   (SQ  + 256 * 512)        // K:  64 x 512B  raw fp32 via cp.async  = 32KB
#define SVT  (SK  + 64 * 512)         // VT: 128 x 256B raw fp32, kv-permuted  = 32KB
#define SM_TOTAL (SVT + 128 * 256)    // 196608 B

// conflict-aware chunk swizzle: LDS.128 phase rows 2p,2p+1 get XORs differing in bit 2
__host__ __device__ __forceinline__ int swz(int r) { return ((r & 1) << 2) | (r >> 1); }

__device__ __forceinline__ uint32_t smem_u32(const void* p) {
    uint32_t a;
    asm("{ .reg .u64 t; cvta.to.shared.u64 t, %1; cvt.u32.u64 %0, t; }" : "=r"(a) : "l"(p));
    return a;
}
__device__ __forceinline__ uint32_t f2tf32(float x) {
    uint32_t r; asm("cvt.rna.tf32.f32 %0, %1;" : "=r"(r) : "f"(x)); return r;
}
__device__ __forceinline__ void cpa16(uint32_t dst, const void* src) {
    asm volatile("cp.async.cg.shared.global [%0], [%1], 16;" :: "r"(dst), "l"(src));
}
__device__ __forceinline__ void cpa4(uint32_t dst, const void* src) {
    asm volatile("cp.async.ca.shared.global [%0], [%1], 4;" :: "r"(dst), "l"(src));
}
#define CP_COMMIT() asm volatile("cp.async.commit_group;" ::: "memory")
#define CP_WAIT(n)  asm volatile("cp.async.wait_group %0;" :: "n"(n) : "memory")

__device__ __forceinline__ void mma_tf32(float* d, uint32_t a0, uint32_t a1,
                                         uint32_t a2, uint32_t a3,
                                         uint32_t b0, uint32_t b1) {
    asm volatile(
        "mma.sync.aligned.m16n8k8.row.col.f32.tf32.tf32.f32 "
        "{%0,%1,%2,%3}, {%4,%5,%6,%7}, {%8,%9}, {%0,%1,%2,%3};"
        : "+f"(d[0]), "+f"(d[1]), "+f"(d[2]), "+f"(d[3])
        : "r"(a0), "r"(a1), "r"(a2), "r"(a3), "r"(b0), "r"(b1));
}
__device__ __forceinline__ uint4 lds128(const char* p) {
    return *(const uint4*)p;
}
#define RNA 0x1000u   // +half-ulp of tf32 before HW truncation == round-nearest-away

__global__ void __launch_bounds__(NTHR, 1)
sparse_attn_mma(const float* __restrict__ q,
                const float* __restrict__ k,
                const float* __restrict__ v,
                const int*   __restrict__ inds,
                float*       __restrict__ out)
{
    extern __shared__ __align__(128) char sm[];
    const uint32_t sbu = smem_u32(sm);

    const int tid  = threadIdx.x;
    const int wid  = tid >> 5;
    const int lane = tid & 31;
    const int lq   = lane >> 2;     // 0..7
    const int lr   = lane & 3;      // 0..3

    const int bid = blockIdx.x;     // 0..511
    const int g   = bid & 15;
    const int bh  = bid >> 4;
    const int qbase = g * 256;

    const float* qp = q + ((size_t)bh * QLEN + qbase) * DIM;
    const float* kb = k + (size_t)bh * KVLEN * DIM;
    const float* vb = v + (size_t)bh * KVLEN * DIM;
    const int*   ib = inds + ((size_t)bh * NG + g) * KPAD;
    float*       op = out + ((size_t)bh * QLEN + qbase) * DIM;

    const float scale = 0.088388347648318447f;   // 1/sqrt(128)

    // K-tile gather: 64 rows x 512B, coalesced 16B cp.async
    #define ISSUE_K(tt) do {                                                      \
        const int* ibn = ib + (tt) * KT;                                          \
        _Pragma("unroll")                                                         \
        for (int i = 0; i < 8; ++i) {                                             \
            const int e = tid + i * NTHR;                                         \
            const int row = e >> 5, c = e & 31;                                   \
            const int gi = __ldg(ibn + row);                                      \
            cpa16(sbu + SK + row * 512 + ((16 * c) ^ (swz(row & 7) << 4)),        \
                  kb + (size_t)gi * DIM + 4 * c);                                 \
        }                                                                         \
    } while (0)

    // VT gather (kv sigma-permuted so QK S-accum regs ARE the PV A-fragment)
    #define ISSUE_V(tt) do {                                                      \
        const int* ibn = ib + (tt) * KT;                                          \
        _Pragma("unroll")                                                         \
        for (int i = 0; i < 8; ++i) {                                             \
            const int p  = wid + 8 * i;                                           \
            const int rr = p & 15;                                                \
            const int dd = (p >> 4) * 32 + lane;                                  \
            const int sbase = 16 * (rr >> 2) + 2 * (rr & 3);                      \
            const uint32_t dbase = sbu + SVT + dd * 256 +                         \
                (((16 * rr) & 0x7F) ^ (swz(dd & 7) << 4)) + ((16 * rr) & 0x80);   \
            const int g0 = __ldg(ibn + sbase + 0);                                \
            const int g1 = __ldg(ibn + sbase + 1);                                \
            const int g2 = __ldg(ibn + sbase + 8);                                \
            const int g3 = __ldg(ibn + sbase + 9);                                \
            cpa4(dbase + 0,  vb + (size_t)g0 * DIM + dd);                         \
            cpa4(dbase + 4,  vb + (size_t)g1 * DIM + dd);                         \
            cpa4(dbase + 8,  vb + (size_t)g2 * DIM + dd);                         \
            cpa4(dbase + 12, vb + (size_t)g3 * DIM + dd);                         \
        }                                                                         \
    } while (0)

    // ---- prologue: start K(0), V(0); load Q (rna + pre-scale) meanwhile ----
    ISSUE_K(0);
    CP_COMMIT();
    ISSUE_V(0);
    CP_COMMIT();

    #pragma unroll
    for (int i = 0; i < 32; ++i) {
        const int e   = tid + i * NTHR;
        const int row = e >> 5, c = e & 31;
        float4 val = ((const float4*)(qp + (size_t)row * DIM))[c];
        uint4 u;
        u.x = f2tf32(val.x * scale); u.y = f2tf32(val.y * scale);
        u.z = f2tf32(val.z * scale); u.w = f2tf32(val.w * scale);
        *(uint4*)(sm + SQ + row * 512 + ((16 * c) ^ (swz(row & 7) << 4))) = u;
    }

    // per-thread constant addressing (warp owns q rows wid*32 .. wid*32+31)
    const int xorA  = swz(lq) << 4;          // row&7 == lq for all 4 A rows
    const char* rbA0 = sm + SQ + (wid * 32 + lq) * 512;
    const char* rbA1 = rbA0 + 8 * 512;
    const char* rbA2 = rbA0 + 16 * 512;
    const char* rbA3 = rbA0 + 24 * 512;
    const int  xorB  = swz(lq) << 4;
    const char* rbK = sm + SK  + lq * 512;
    const char* rbV = sm + SVT + lq * 256;

    float oacc[2][16][4];
    #pragma unroll
    for (int m = 0; m < 2; ++m)
        #pragma unroll
        for (int j = 0; j < 16; ++j)
            #pragma unroll
            for (int c = 0; c < 4; ++c) oacc[m][j][c] = 0.0f;
    float l0 = 0.0f, l1 = 0.0f, l2 = 0.0f, l3 = 0.0f;

    for (int t = 0; t < NTILES; ++t) {
        CP_WAIT(1);          // K(t) arrived (V(t) or K(t+?) may still be pending)
        __syncthreads();

        // ---- QK: S[32 x 64] per warp; B frags shared across both m16 tiles ----
        float sacc[2][8][4];
        #pragma unroll
        for (int m = 0; m < 2; ++m)
            #pragma unroll
            for (int j = 0; j < 8; ++j)
                #pragma unroll
                for (int c = 0; c < 4; ++c) sacc[m][j][c] = 0.0f;

        #pragma unroll
        for (int pr = 0; pr < 8; ++pr) {
            const int abyte = (64 * pr + 16 * lr) ^ xorA;
            const uint4 A0 = lds128(rbA0 + abyte);
            const uint4 A1 = lds128(rbA1 + abyte);
            const uint4 A2 = lds128(rbA2 + abyte);
            const uint4 A3 = lds128(rbA3 + abyte);
            const int bbyte = (64 * pr + 16 * lr) ^ xorB;
            #pragma unroll
            for (int j = 0; j < 8; ++j) {
                uint4 B = lds128(rbK + j * (8 * 512) + bbyte);
                B.x += RNA; B.y += RNA; B.z += RNA; B.w += RNA;
                mma_tf32(sacc[0][j], A0.x, A1.x, A0.y, A1.y, B.x, B.y);
                mma_tf32(sacc[0][j], A0.z, A1.z, A0.w, A1.w, B.z, B.w);
                mma_tf32(sacc[1][j], A2.x, A3.x, A2.y, A3.y, B.x, B.y);
                mma_tf32(sacc[1][j], A2.z, A3.z, A2.w, A3.w, B.z, B.w);
            }
        }
        __syncthreads();     // all warps done reading K(t)
        if (t + 1 < NTILES) { ISSUE_K(t + 1); CP_COMMIT(); }

        // ---- softmax (warp-local): exp, row sums, P -> regs (PV A-frag order) ----
        uint32_t* pf = reinterpret_cast<uint32_t*>(&sacc[0][0][0]);
        {
            float sA = 0.0f, sB = 0.0f, sC = 0.0f, sD = 0.0f;
            #pragma unroll
            for (int j = 0; j < 8; ++j) {
                const float e0 = __expf(fminf(sacc[0][j][0], 60.0f));
                const float e1 = __expf(fminf(sacc[0][j][1], 60.0f));
                const float e2 = __expf(fminf(sacc[0][j][2], 60.0f));
                const float e3 = __expf(fminf(sacc[0][j][3], 60.0f));
                sA += e0 + e1;  sB += e2 + e3;
                pf[4 * j + 0] = f2tf32(e0);
                pf[4 * j + 1] = f2tf32(e2);
                pf[4 * j + 2] = f2tf32(e1);
                pf[4 * j + 3] = f2tf32(e3);
                const float f0 = __expf(fminf(sacc[1][j][0], 60.0f));
                const float f1 = __expf(fminf(sacc[1][j][1], 60.0f));
                const float f2 = __expf(fminf(sacc[1][j][2], 60.0f));
                const float f3 = __expf(fminf(sacc[1][j][3], 60.0f));
                sC += f0 + f1;  sD += f2 + f3;
                pf[32 + 4 * j + 0] = f2tf32(f0);
                pf[32 + 4 * j + 1] = f2tf32(f2);
                pf[32 + 4 * j + 2] = f2tf32(f1);
                pf[32 + 4 * j + 3] = f2tf32(f3);
            }
            sA += __shfl_xor_sync(0xffffffffu, sA, 1);
            sA += __shfl_xor_sync(0xffffffffu, sA, 2);
            sB += __shfl_xor_sync(0xffffffffu, sB, 1);
            sB += __shfl_xor_sync(0xffffffffu, sB, 2);
            sC += __shfl_xor_sync(0xffffffffu, sC, 1);
            sC += __shfl_xor_sync(0xffffffffu, sC, 2);
            sD += __shfl_xor_sync(0xffffffffu, sD, 1);
            sD += __shfl_xor_sync(0xffffffffu, sD, 2);
            l0 += sA;  l1 += sB;  l2 += sC;  l3 += sD;
        }

        // ---- wait V(t); PV: O[32 x 128] += P x V (B frags shared across mt) ----
        if (t + 1 < NTILES) { CP_WAIT(1); } else { CP_WAIT(0); }
        __syncthreads();

        #pragma unroll
        for (int pr = 0; pr < 4; ++pr) {
            const int vv = 64 * pr + 16 * lr;
            const int vbyte = ((vv & 0x7F) ^ xorB) + (vv & 0x80);
            const uint32_t* pa0 = pf + 8 * pr;
            const uint32_t* pa1 = pf + 32 + 8 * pr;
            #pragma unroll
            for (int j = 0; j < 16; ++j) {
                uint4 B = lds128(rbV + j * (8 * 256) + vbyte);
                B.x += RNA; B.y += RNA; B.z += RNA; B.w += RNA;
                mma_tf32(oacc[0][j], pa0[0], pa0[1], pa0[2], pa0[3], B.x, B.y);
                mma_tf32(oacc[0][j], pa0[4], pa0[5], pa0[6], pa0[7], B.z, B.w);
                mma_tf32(oacc[1][j], pa1[0], pa1[1], pa1[2], pa1[3], B.x, B.y);
                mma_tf32(oacc[1][j], pa1[4], pa1[5], pa1[6], pa1[7], B.z, B.w);
            }
        }
        __syncthreads();     // all warps done reading VT(t)
        if (t + 1 < NTILES) { ISSUE_V(t + 1); CP_COMMIT(); }
    }

    // ---- epilogue: divide by l, store ----
    const float i0 = 1.0f / l0, i1 = 1.0f / l1, i2 = 1.0f / l2, i3 = 1.0f / l3;
    {
        float* r0 = op + (size_t)(wid * 32 + lq) * DIM;
        float* r1 = r0 + 8 * DIM;
        float* r2 = r0 + 16 * DIM;
        float* r3 = r0 + 24 * DIM;
        #pragma unroll
        for (int j = 0; j < 16; ++j) {
            const int col = 8 * j + 2 * lr;
            float2 a, b, c, d;
            a.x = oacc[0][j][0] * i0;  a.y = oacc[0][j][1] * i0;
            b.x = oacc[0][j][2] * i1;  b.y = oacc[0][j][3] * i1;
            c.x = oacc[1][j][0] * i2;  c.y = oacc[1][j][1] * i2;
            d.x = oacc[1][j][2] * i3;  d.y = oacc[1][j][3] * i3;
            *(float2*)(r0 + col) = a;
            *(float2*)(r1 + col) = b;
            *(float2*)(r2 + col) = c;
            *(float2*)(r3 + col) = d;
        }
    }
}

extern "C" void kernel_launch(void* const* d_in, const int* in_sizes, int n_in,
                              void* d_out, int out_size)
{
    const float* q    = (const float*)d_in[0];
    const float* k    = (const float*)d_in[1];
    const float* v    = (const float*)d_in[2];
    const int*   inds = (const int*)d_in[3];
    float*       out  = (float*)d_out;

    cudaFuncSetAttribute(sparse_attn_mma,
                         cudaFuncAttributeMaxDynamicSharedMemorySize, SM_TOTAL);

    const int grid = NBH * NG;   // 512
    sparse_attn_mma<<<grid, NTHR, SM_TOTAL>>>(q, k, v, inds, out);
}